// round 10
// baseline (speedup 1.0000x reference)
#include <cuda_runtime.h>
#include <cstdint>

// CRPS, persistent double-buffered cp.async.bulk pipeline.
// 256 CTAs x 4 tiles of 256 px. Tile t computes while tile t+1 streams in;
// tile t+2 is issued into the freed buffer after the post-compute barrier.
// term2 via sort identity sum_{i<j}|xi-xj| = sum_k (2k-15) x_(k)
// (Batcher-16 network, FMNMX/ALU pipe). Last-block finalize, self-resetting
// counter (graph-replay deterministic).

#define NS   16
#define P    262144
#define NT   256
#define TW   256                 // pixels per tile
#define TPB  4                   // tiles per block
#define NBK  (P / (TW * TPB))    // 256 blocks
#define TILE_B (NS * TW * 4)     // 16384 bytes

__device__ float        g_partial[NBK];
__device__ unsigned int g_count = 0;

__device__ __forceinline__ uint32_t smem_u32(const void* p) {
    uint32_t a;
    asm("{ .reg .u64 t; cvta.to.shared.u64 t, %1; cvt.u32.u64 %0, t; }"
        : "=r"(a) : "l"(p));
    return a;
}

__device__ __forceinline__ void mbar_wait(uint32_t mb, uint32_t parity) {
    uint32_t done;
    asm volatile(
        "{\n\t.reg .pred p;\n\t"
        "mbarrier.try_wait.parity.acquire.cta.shared::cta.b64 p, [%1], %2;\n\t"
        "selp.b32 %0, 1, 0, p;\n\t}"
        : "=r"(done) : "r"(mb), "r"(parity) : "memory");
    if (!done) {
        asm volatile(
            "{\n\t.reg .pred P1;\n\t"
            "W_%=:\n\t"
            "mbarrier.try_wait.parity.acquire.cta.shared::cta.b64 P1, [%0], %1, 0x989680;\n\t"
            "@P1 bra.uni D_%=;\n\t"
            "bra.uni W_%=;\n\t"
            "D_%=:\n\t}"
            :: "r"(mb), "r"(parity) : "memory");
    }
}

__device__ __forceinline__ void issue_tile(const float* __restrict__ s,
                                           int tile, float* buf, uint32_t mb) {
    asm volatile("mbarrier.arrive.expect_tx.shared.b64 _, [%0], %1;"
                 :: "r"(mb), "r"((uint32_t)TILE_B) : "memory");
#pragma unroll
    for (int i = 0; i < NS; i++) {
        const float* src = s + (size_t)i * P + (size_t)tile * TW;
        uint32_t dst = smem_u32(buf + i * TW);
        asm volatile(
            "cp.async.bulk.shared::cta.global.mbarrier::complete_tx::bytes "
            "[%0], [%1], %2, [%3];"
            :: "r"(dst), "l"(src), "r"(TW * 4u), "r"(mb) : "memory");
    }
}

__device__ __forceinline__ void cas(float& a, float& b) {
    float lo = fminf(a, b);
    float hi = fmaxf(a, b);
    a = lo; b = hi;
}

__device__ __forceinline__ float crps_px(float v[NS], float t) {
    float a1 = 0.f;
#pragma unroll
    for (int i = 0; i < NS; i++) a1 += fabsf(v[i] - t);

    // Batcher odd-even mergesort, n=16 (63 CAS)
#pragma unroll
    for (int pp = 1; pp < NS; pp <<= 1) {
#pragma unroll
        for (int k = pp; k >= 1; k >>= 1) {
#pragma unroll
            for (int j = k % pp; j + k < NS; j += 2 * k) {
#pragma unroll
                for (int i = 0; i < k && i + j + k < NS; i++) {
                    if ((i + j) / (2 * pp) == (i + j + k) / (2 * pp))
                        cas(v[i + j], v[i + j + k]);
                }
            }
        }
    }

    float a2 = 0.f;
#pragma unroll
    for (int k = 0; k < NS; k++)
        a2 = fmaf((float)(2 * k - 15), v[k], a2);

    return a1 * (1.0f / 16.0f) - a2 * (1.0f / 256.0f);
}

__global__ void __launch_bounds__(NT)
k_crps(const float* __restrict__ s, const float* __restrict__ y,
       float* __restrict__ out) {
    __shared__ __align__(128) float buf[2][NS][TW];   // 32 KB
    __shared__ __align__(8)  uint64_t mbar[2];

    const int tid   = threadIdx.x;
    const int tile0 = blockIdx.x * TPB;
    const uint32_t mb0 = smem_u32(&mbar[0]);
    const uint32_t mb1 = smem_u32(&mbar[1]);

    if (tid == 0) {
        asm volatile("mbarrier.init.shared.b64 [%0], %1;" :: "r"(mb0), "r"(1u) : "memory");
        asm volatile("mbarrier.init.shared.b64 [%0], %1;" :: "r"(mb1), "r"(1u) : "memory");
    }
    __syncthreads();

    if (tid == 0) {
        issue_tile(s, tile0 + 0, &buf[0][0][0], mb0);   // prologue: 2 tiles in flight
        issue_tile(s, tile0 + 1, &buf[1][0][0], mb1);
    }

    float val = 0.f;
#pragma unroll
    for (int t = 0; t < TPB; t++) {
        const int b  = t & 1;
        const uint32_t ph = (t >> 1) & 1;
        const uint32_t mb = b ? mb1 : mb0;

        // target load in flight while this tile's bulk copy finishes
        const float tv = __ldg(&y[(tile0 + t) * TW + tid]);

        mbar_wait(mb, ph);

        float v[NS];
#pragma unroll
        for (int i = 0; i < NS; i++) v[i] = buf[b][i][tid];
        val += crps_px(v, tv);

        __syncthreads();                    // all warps done reading buf[b]
        if (t + 2 < TPB && tid == 0)
            issue_tile(s, tile0 + t + 2, &buf[b][0][0], mb);  // streams under tile t+1's compute
    }

    // Block reduction
#pragma unroll
    for (int o = 16; o > 0; o >>= 1)
        val += __shfl_xor_sync(0xFFFFFFFFu, val, o);

    __shared__ float sm[NT / 32];
    const int lane = tid & 31;
    const int wid  = tid >> 5;
    if (lane == 0) sm[wid] = val;
    __syncthreads();

    if (wid == 0) {
        float w = (lane < NT / 32) ? sm[lane] : 0.f;
#pragma unroll
        for (int o = 4; o > 0; o >>= 1)
            w += __shfl_xor_sync(0xFFFFFFFFu, w, o);
        if (lane == 0) g_partial[blockIdx.x] = w;
    }

    // Last-block finalize (counter self-resets -> graph-replay deterministic)
    __shared__ bool isLast;
    if (tid == 0) {
        __threadfence();
        isLast = (atomicAdd(&g_count, 1u) == NBK - 1);
    }
    __syncthreads();

    if (isLast) {
        __threadfence();
        double d = (double)g_partial[tid];    // NBK == NT
#pragma unroll
        for (int o = 16; o > 0; o >>= 1)
            d += __shfl_xor_sync(0xFFFFFFFFu, d, o);

        __shared__ double sd[NT / 32];
        if (lane == 0) sd[wid] = d;
        __syncthreads();
        if (wid == 0) {
            double e = (lane < NT / 32) ? sd[lane] : 0.0;
#pragma unroll
            for (int o = 4; o > 0; o >>= 1)
                e += __shfl_xor_sync(0xFFFFFFFFu, e, o);
            if (lane == 0) {
                *out = (float)(e * (1.0 / (double)P));
                g_count = 0;
            }
        }
    }
}

extern "C" void kernel_launch(void* const* d_in, const int* in_sizes, int n_in,
                              void* d_out, int out_size) {
    const float* samples = (const float*)d_in[0];
    const float* target  = (const float*)d_in[1];
    k_crps<<<NBK, NT>>>(samples, target, (float*)d_out);
}

// round 11
// speedup vs baseline: 1.1831x; 1.1831x over previous
#include <cuda_runtime.h>

// CRPS loss. Best-known structure (R6: 512x256, 2px/thread) with the two
// pixels fused as float2: 16 LDG.64 (half the LSU/L1tex traffic of 32
// LDG.32) and ONE interleaved Batcher-16 network (cas2 = 4 FMNMX) so the
// two sort dependency chains overlap instead of running serially.
// term2 via sort identity sum_{i<j}|xi-xj| = sum_k (2k-15) x_(k).

#define NS  16
#define P   262144
#define NT  256
#define NB  (P / (2 * NT))      // 512 blocks, thread handles pixels 2g, 2g+1

__device__ float        g_partial[NB];
__device__ unsigned int g_count = 0;

__device__ __forceinline__ void cas2(float2& a, float2& b) {
    float2 lo, hi;
    lo.x = fminf(a.x, b.x); hi.x = fmaxf(a.x, b.x);
    lo.y = fminf(a.y, b.y); hi.y = fmaxf(a.y, b.y);
    a = lo; b = hi;
}

__global__ void __launch_bounds__(NT)
k_crps(const float2* __restrict__ s2, const float2* __restrict__ y2,
       float* __restrict__ out) {
    const int g = blockIdx.x * NT + threadIdx.x;   // float2 index

    // 16 coalesced LDG.64 (256B/warp each), front-batched; + 1 target LDG.64
    float2 v[NS];
#pragma unroll
    for (int i = 0; i < NS; i++) v[i] = s2[i * (P / 2) + g];
    const float2 t = y2[g];

    // term1: sum_i |s_i - y| for both pixels (two independent FADD chains)
    float a1x = 0.f, a1y = 0.f;
#pragma unroll
    for (int i = 0; i < NS; i++) {
        a1x += fabsf(v[i].x - t.x);
        a1y += fabsf(v[i].y - t.y);
    }

    // Interleaved Batcher odd-even mergesort, n=16 (63 cas2 = 252 FMNMX)
#pragma unroll
    for (int pp = 1; pp < NS; pp <<= 1) {
#pragma unroll
        for (int k = pp; k >= 1; k >>= 1) {
#pragma unroll
            for (int j = k % pp; j + k < NS; j += 2 * k) {
#pragma unroll
                for (int i = 0; i < k && i + j + k < NS; i++) {
                    if ((i + j) / (2 * pp) == (i + j + k) / (2 * pp))
                        cas2(v[i + j], v[i + j + k]);
                }
            }
        }
    }

    // term2 raw: sum_k (2k-15) x_(k), both pixels
    float a2x = 0.f, a2y = 0.f;
#pragma unroll
    for (int k = 0; k < NS; k++) {
        const float c = (float)(2 * k - 15);
        a2x = fmaf(c, v[k].x, a2x);
        a2y = fmaf(c, v[k].y, a2y);
    }

    float val = (a1x + a1y) * (1.0f / 16.0f) - (a2x + a2y) * (1.0f / 256.0f);

    // Block reduction
#pragma unroll
    for (int o = 16; o > 0; o >>= 1)
        val += __shfl_xor_sync(0xFFFFFFFFu, val, o);

    __shared__ float sm[NT / 32];
    const int lane = threadIdx.x & 31;
    const int wid  = threadIdx.x >> 5;
    if (lane == 0) sm[wid] = val;
    __syncthreads();

    if (wid == 0) {
        float w = (lane < NT / 32) ? sm[lane] : 0.f;
#pragma unroll
        for (int o = 4; o > 0; o >>= 1)
            w += __shfl_xor_sync(0xFFFFFFFFu, w, o);
        if (lane == 0) g_partial[blockIdx.x] = w;
    }

    // Last-block finalize (counter self-resets -> graph-replay deterministic)
    __shared__ bool isLast;
    if (threadIdx.x == 0) {
        __threadfence();
        isLast = (atomicAdd(&g_count, 1u) == NB - 1);
    }
    __syncthreads();

    if (isLast) {
        __threadfence();
        double d = 0.0;
#pragma unroll
        for (int r = 0; r < NB / NT; r++)
            d += (double)g_partial[threadIdx.x + r * NT];
#pragma unroll
        for (int o = 16; o > 0; o >>= 1)
            d += __shfl_xor_sync(0xFFFFFFFFu, d, o);

        __shared__ double sd[NT / 32];
        if (lane == 0) sd[wid] = d;
        __syncthreads();
        if (wid == 0) {
            double e = (lane < NT / 32) ? sd[lane] : 0.0;
#pragma unroll
            for (int o = 4; o > 0; o >>= 1)
                e += __shfl_xor_sync(0xFFFFFFFFu, e, o);
            if (lane == 0) {
                *out = (float)(e * (1.0 / (double)P));
                g_count = 0;
            }
        }
    }
}

extern "C" void kernel_launch(void* const* d_in, const int* in_sizes, int n_in,
                              void* d_out, int out_size) {
    const float2* samples = (const float2*)d_in[0];
    const float2* target  = (const float2*)d_in[1];
    k_crps<<<NB, NT>>>(samples, target, (float*)d_out);
}

// round 13
// speedup vs baseline: 1.2113x; 1.0238x over previous
#include <cuda_runtime.h>

// CRPS loss. R6 layout (512x256, 2px/thread, scalar LDG.32) + two-phase
// in-thread pipeline: batch A = samples[0..8) both px + targets (18 LDG),
// partial term1 + sort8 of each half; batch B = samples[8..16) (16 LDG)
// issued right after batch A is consumed (empty-asm dependency), landing
// while sort8 runs. Batcher pp=1,2,4 phases == two sort8s; pp=8 == merge.
// term2 via sum_{i<j}|xi-xj| = sum_k (2k-15) x_(k).

#define NS     16
#define H      8
#define P      262144
#define NT     256
#define NB     (P / (2 * NT))   // 512
#define STRIDE (NB * NT)        // 131072

__device__ float        g_partial[NB];
__device__ unsigned int g_count = 0;

__device__ __forceinline__ void cas(float& a, float& b) {
    float lo = fminf(a, b);
    float hi = fmaxf(a, b);
    a = lo; b = hi;
}

// Batcher odd-even mergesort phases pp=1,2,4 on 8 elems (19 CAS)
__device__ __forceinline__ void sort8(float* v) {
#pragma unroll
    for (int pp = 1; pp < H; pp <<= 1) {
#pragma unroll
        for (int k = pp; k >= 1; k >>= 1) {
#pragma unroll
            for (int j = k % pp; j + k < H; j += 2 * k) {
#pragma unroll
                for (int i = 0; i < k && i + j + k < H; i++) {
                    if ((i + j) / (2 * pp) == (i + j + k) / (2 * pp))
                        cas(v[i + j], v[i + j + k]);
                }
            }
        }
    }
}

// pp=8 phase of Batcher-16: merge two sorted 8-halves (25 CAS)
__device__ __forceinline__ void merge16(float* v) {
    const int pp = H;
#pragma unroll
    for (int k = pp; k >= 1; k >>= 1) {
#pragma unroll
        for (int j = k % pp; j + k < NS; j += 2 * k) {
#pragma unroll
            for (int i = 0; i < k && i + j + k < NS; i++) {
                if ((i + j) / (2 * pp) == (i + j + k) / (2 * pp))
                    cas(v[i + j], v[i + j + k]);
            }
        }
    }
}

__global__ void __launch_bounds__(NT, 4)
k_crps(const float* __restrict__ s, const float* __restrict__ y,
       float* __restrict__ out) {
    const int p0 = blockIdx.x * NT + threadIdx.x;
    const int p1 = p0 + STRIDE;

    float v0[NS], v1[NS];

    // ---- batch A: first 8 samples of both pixels + targets (18 LDG) ----
#pragma unroll
    for (int i = 0; i < H; i++) v0[i] = __ldg(&s[i * P + p0]);
#pragma unroll
    for (int i = 0; i < H; i++) v1[i] = __ldg(&s[i * P + p1]);
    const float t0 = __ldg(&y[p0]);
    const float t1 = __ldg(&y[p1]);

    // consume batch A: partial term1
    float a1 = 0.f;
#pragma unroll
    for (int i = 0; i < H; i++)
        a1 += fabsf(v0[i] - t0) + fabsf(v1[i] - t1);

    // force batch-B load issue AFTER batch A is consumed (but overlapping
    // the sort8 compute below): fake data dependency, zero instructions.
    int q0 = p0, q1 = p1;
    asm volatile("" : "+r"(q0), "+r"(q1) : "f"(a1));

    // ---- batch B: second 8 samples (16 LDG), in flight during sort8 ----
#pragma unroll
    for (int i = H; i < NS; i++) v0[i] = __ldg(&s[i * P + q0]);
#pragma unroll
    for (int i = H; i < NS; i++) v1[i] = __ldg(&s[i * P + q1]);

    // overlap: sort first halves while batch B streams
    sort8(v0);
    sort8(v1);

    // consume batch B
#pragma unroll
    for (int i = H; i < NS; i++)
        a1 += fabsf(v0[i] - t0) + fabsf(v1[i] - t1);
    sort8(v0 + H);
    sort8(v1 + H);
    merge16(v0);
    merge16(v1);

    // term2 raw: sum_k (2k-15) x_(k), both pixels
    float a2 = 0.f;
#pragma unroll
    for (int k = 0; k < NS; k++) {
        const float c = (float)(2 * k - 15);
        a2 = fmaf(c, v0[k] + v1[k], a2);
    }

    float val = a1 * (1.0f / 16.0f) - a2 * (1.0f / 256.0f);

    // Block reduction
#pragma unroll
    for (int o = 16; o > 0; o >>= 1)
        val += __shfl_xor_sync(0xFFFFFFFFu, val, o);

    __shared__ float sm[NT / 32];
    const int lane = threadIdx.x & 31;
    const int wid  = threadIdx.x >> 5;
    if (lane == 0) sm[wid] = val;
    __syncthreads();

    if (wid == 0) {
        float w = (lane < NT / 32) ? sm[lane] : 0.f;
#pragma unroll
        for (int o = 4; o > 0; o >>= 1)
            w += __shfl_xor_sync(0xFFFFFFFFu, w, o);
        if (lane == 0) g_partial[blockIdx.x] = w;
    }

    // Last-block finalize (counter self-resets -> graph-replay deterministic)
    __shared__ bool isLast;
    if (threadIdx.x == 0) {
        __threadfence();
        isLast = (atomicAdd(&g_count, 1u) == NB - 1);
    }
    __syncthreads();

    if (isLast) {
        __threadfence();
        double d = 0.0;
#pragma unroll
        for (int r = 0; r < NB / NT; r++)
            d += (double)g_partial[threadIdx.x + r * NT];
#pragma unroll
        for (int o = 16; o > 0; o >>= 1)
            d += __shfl_xor_sync(0xFFFFFFFFu, d, o);

        __shared__ double sd[NT / 32];
        if (lane == 0) sd[wid] = d;
        __syncthreads();
        if (wid == 0) {
            double e = (lane < NT / 32) ? sd[lane] : 0.0;
#pragma unroll
            for (int o = 4; o > 0; o >>= 1)
                e += __shfl_xor_sync(0xFFFFFFFFu, e, o);
            if (lane == 0) {
                *out = (float)(e * (1.0 / (double)P));
                g_count = 0;
            }
        }
    }
}

extern "C" void kernel_launch(void* const* d_in, const int* in_sizes, int n_in,
                              void* d_out, int out_size) {
    const float* samples = (const float*)d_in[0];
    const float* target  = (const float*)d_in[1];
    k_crps<<<NB, NT>>>(samples, target, (float*)d_out);
}